// round 2
// baseline (speedup 1.0000x reference)
#include <cuda_runtime.h>
#include <math.h>

#define TTOK 2048
#define DDIM 1024
#define TD (TTOK*DDIM)

// ---------------- scratch (static device memory; no allocations) ----------------
__device__ float g_scratch[40304640];

#define OFF_DX    ((size_t)0)
#define OFF_Z     ((size_t)TD)
#define OFF_XW    ((size_t)2*TD)
#define OFF_XPROJ ((size_t)3*TD)   // [0]=xr [1]=xk [2]=xv [3]=xg
#define OFF_RKVG  ((size_t)7*TD)   // [0]=r  [1]=k  [2]=v  [3]=g(silu)
#define OFF_W     ((size_t)11*TD)
#define OFF_CS    ((size_t)12*TD)
#define OFF_R1    ((size_t)13*TD)
#define OFF_K1    ((size_t)14*TD)
#define OFF_R2    ((size_t)15*TD)
#define OFF_K2    ((size_t)16*TD)
#define OFF_Y     ((size_t)17*TD)
#define OFF_YG    ((size_t)18*TD)
#define OFF_XXX   ((size_t)19*TD)                 // 2048*160
#define OFF_WMID  (OFF_XXX + (size_t)TTOK*160)    // 2048*64

static __device__ __forceinline__ float clip60(float x) {
    return fminf(fmaxf(x, -60.f), 60.f);
}

// ---------------- 1. token shift + z = x + dx*maa_x ----------------
__global__ __launch_bounds__(256) void prep_k(const float* __restrict__ x,
                                              const float* __restrict__ maa_x,
                                              float* __restrict__ dx,
                                              float* __restrict__ z) {
    int idx = blockIdx.x * 256 + threadIdx.x;
    if (idx >= TD) return;
    int t = idx >> 10;
    int d = idx & 1023;
    float xv = x[idx];
    float prev = (t > 0) ? x[idx - 1024] : 0.f;
    float nxt  = (t < TTOK - 1) ? x[idx + 1024] : 0.f;
    float dxv = 0.5f * (prev + nxt) - xv;
    dx[idx] = dxv;
    z[idx]  = xv + dxv * maa_x[d];
}

// ---------------- 2. xxx = tanh(z @ maa_w1)   (2048 x 160) ----------------
__global__ __launch_bounds__(160) void xxx_k(const float* __restrict__ z,
                                             const float* __restrict__ w1,
                                             float* __restrict__ xxx) {
    __shared__ float zs[4][1024];
    int t0 = blockIdx.x * 4;
    int tid = threadIdx.x;
    for (int i = tid; i < 4 * 1024; i += 160) {
        int r = i >> 10, c = i & 1023;
        zs[r][c] = z[(size_t)(t0 + r) * 1024 + c];
    }
    __syncthreads();
    float acc[4] = {0.f, 0.f, 0.f, 0.f};
    for (int d = 0; d < 1024; d++) {
        float w = w1[d * 160 + tid];
        acc[0] += zs[0][d] * w;
        acc[1] += zs[1][d] * w;
        acc[2] += zs[2][d] * w;
        acc[3] += zs[3][d] * w;
    }
#pragma unroll
    for (int r = 0; r < 4; r++)
        xxx[(size_t)(t0 + r) * 160 + tid] = tanhf(acc[r]);
}

// ---------------- 3. mixer: m_f = xxx_f @ maa_w2_f ; build xw/xk/xv/xr/xg ----------------
__global__ __launch_bounds__(256) void mix_k(const float* __restrict__ x,
                                             const float* __restrict__ dx,
                                             const float* __restrict__ xxx,
                                             const float* __restrict__ w2,
                                             const float* __restrict__ maa_w,
                                             const float* __restrict__ maa_k,
                                             const float* __restrict__ maa_v,
                                             const float* __restrict__ maa_r,
                                             const float* __restrict__ maa_g,
                                             float* __restrict__ xw,
                                             float* __restrict__ xproj) {
    __shared__ float xs[4][160];
    int t0 = blockIdx.x * 4;
    int tid = threadIdx.x;
    for (int i = tid; i < 640; i += 256) {
        int r = i / 160, c = i - r * 160;
        xs[r][c] = xxx[(size_t)(t0 + r) * 160 + c];
    }
    __syncthreads();
    int d = tid * 4;
    float4 xv[4], dxv[4];
#pragma unroll
    for (int r = 0; r < 4; r++) {
        xv[r]  = *(const float4*)(x  + (size_t)(t0 + r) * 1024 + d);
        dxv[r] = *(const float4*)(dx + (size_t)(t0 + r) * 1024 + d);
    }
#pragma unroll
    for (int f = 0; f < 5; f++) {
        float4 acc[4];
#pragma unroll
        for (int r = 0; r < 4; r++) acc[r] = make_float4(0.f, 0.f, 0.f, 0.f);
        for (int mi = 0; mi < 32; mi++) {
            float4 w = *(const float4*)(w2 + (size_t)(f * 32 + mi) * 1024 + d);
#pragma unroll
            for (int r = 0; r < 4; r++) {
                float s = xs[r][f * 32 + mi];
                acc[r].x += s * w.x; acc[r].y += s * w.y;
                acc[r].z += s * w.z; acc[r].w += s * w.w;
            }
        }
        const float* maa = (f == 0) ? maa_w : (f == 1) ? maa_k : (f == 2) ? maa_v
                         : (f == 3) ? maa_r : maa_g;
        float4 mv = *(const float4*)(maa + d);
        float* outp;
        if (f == 0)      outp = xw;
        else if (f == 1) outp = xproj + (size_t)1 * TD;  // xk
        else if (f == 2) outp = xproj + (size_t)2 * TD;  // xv
        else if (f == 3) outp = xproj;                   // xr
        else             outp = xproj + (size_t)3 * TD;  // xg
#pragma unroll
        for (int r = 0; r < 4; r++) {
            float4 o;
            o.x = xv[r].x + dxv[r].x * (mv.x + acc[r].x);
            o.y = xv[r].y + dxv[r].y * (mv.y + acc[r].y);
            o.z = xv[r].z + dxv[r].z * (mv.z + acc[r].z);
            o.w = xv[r].w + dxv[r].w * (mv.w + acc[r].w);
            *(float4*)(outp + (size_t)(t0 + r) * 1024 + d) = o;
        }
    }
}

// ---------------- 4. SGEMM 128x128x16, 8x8 microtile (batched over z) ----------------
__global__ __launch_bounds__(256) void sgemm_k(const float* __restrict__ A,
                                               const float* __restrict__ B0,
                                               const float* __restrict__ B1,
                                               const float* __restrict__ B2,
                                               const float* __restrict__ B3,
                                               float* __restrict__ C,
                                               int M, int N, int K,
                                               size_t strideA, size_t strideC,
                                               int siluZ) {
    __shared__ float As[16][132];
    __shared__ float Bs[16][132];
    int z = blockIdx.z;
    const float* Bsel = (z == 0) ? B0 : (z == 1) ? B1 : (z == 2) ? B2 : B3;
    const float* Ab = A + (size_t)z * strideA;
    float* Cb = C + (size_t)z * strideC;
    int tid = threadIdx.x;
    int bm = blockIdx.y * 128, bn = blockIdx.x * 128;
    int arow = tid >> 2;
    int acol = (tid & 3) * 4;
    int brow = tid >> 5;
    int bcol = (tid & 31) * 4;
    int ty = tid >> 4, tx = tid & 15;
    float acc[8][8];
#pragma unroll
    for (int i = 0; i < 8; i++)
#pragma unroll
        for (int j = 0; j < 8; j++) acc[i][j] = 0.f;

    for (int k0 = 0; k0 < K; k0 += 16) {
#pragma unroll
        for (int r = 0; r < 2; r++) {
            int row = arow + r * 64;
            float4 a = *(const float4*)(Ab + (size_t)(bm + row) * K + k0 + acol);
            As[acol + 0][row] = a.x;
            As[acol + 1][row] = a.y;
            As[acol + 2][row] = a.z;
            As[acol + 3][row] = a.w;
        }
#pragma unroll
        for (int r = 0; r < 2; r++) {
            int row = brow + r * 8;
            float4 b = *(const float4*)(Bsel + (size_t)(k0 + row) * N + bn + bcol);
            *(float4*)(&Bs[row][bcol]) = b;
        }
        __syncthreads();
#pragma unroll
        for (int kk = 0; kk < 16; kk++) {
            float a[8], b[8];
            *(float4*)(a)     = *(const float4*)(&As[kk][ty * 8]);
            *(float4*)(a + 4) = *(const float4*)(&As[kk][ty * 8 + 4]);
            *(float4*)(b)     = *(const float4*)(&Bs[kk][tx * 8]);
            *(float4*)(b + 4) = *(const float4*)(&Bs[kk][tx * 8 + 4]);
#pragma unroll
            for (int i = 0; i < 8; i++)
#pragma unroll
                for (int j = 0; j < 8; j++) acc[i][j] += a[i] * b[j];
        }
        __syncthreads();
    }
    bool silu = (z == siluZ);
#pragma unroll
    for (int i = 0; i < 8; i++) {
        float o[8];
#pragma unroll
        for (int j = 0; j < 8; j++) {
            float v = acc[i][j];
            if (silu) v = v / (1.f + expf(-v));
            o[j] = v;
        }
        float* cp = Cb + (size_t)(bm + ty * 8 + i) * N + bn + tx * 8;
        *(float4*)(cp)     = *(float4*)(o);
        *(float4*)(cp + 4) = *(float4*)(o + 4);
    }
}

// ---------------- 5. decay MLP stage 1: wmid = tanh(xw @ decay_w1)  (2048 x 64) ----------------
__global__ __launch_bounds__(64) void decay1_k(const float* __restrict__ xw,
                                               const float* __restrict__ dw1,
                                               float* __restrict__ wmid) {
    __shared__ float xs[8][1024];
    int t0 = blockIdx.x * 8;
    int tid = threadIdx.x;
    for (int i = tid; i < 8 * 256; i += 64) {
        int r = i >> 8;
        int c4 = (i & 255) * 4;
        *(float4*)(&xs[r][c4]) = *(const float4*)(xw + (size_t)(t0 + r) * 1024 + c4);
    }
    __syncthreads();
    float acc[8] = {0.f, 0.f, 0.f, 0.f, 0.f, 0.f, 0.f, 0.f};
    for (int d = 0; d < 1024; d++) {
        float w = dw1[d * 64 + tid];
#pragma unroll
        for (int r = 0; r < 8; r++) acc[r] += xs[r][d] * w;
    }
#pragma unroll
    for (int r = 0; r < 8; r++)
        wmid[(size_t)(t0 + r) * 64 + tid] = tanhf(acc[r]);
}

// ---------------- 6. decay MLP stage 2: w = time_decay + wmid @ decay_w2 ----------------
__global__ __launch_bounds__(256) void decay2_k(const float* __restrict__ wmid,
                                                const float* __restrict__ dw2,
                                                const float* __restrict__ td,
                                                float* __restrict__ w) {
    __shared__ float ws[4][64];
    int t0 = blockIdx.x * 4;
    int tid = threadIdx.x;
    {
        int r = tid >> 6, c = tid & 63;
        ws[r][c] = wmid[(size_t)(t0 + r) * 64 + c];
    }
    __syncthreads();
    int d = tid * 4;
    float4 tdv = *(const float4*)(td + d);
    float4 acc[4];
#pragma unroll
    for (int r = 0; r < 4; r++) acc[r] = tdv;
    for (int j = 0; j < 64; j++) {
        float4 wv = *(const float4*)(dw2 + (size_t)j * 1024 + d);
#pragma unroll
        for (int r = 0; r < 4; r++) {
            float s = ws[r][j];
            acc[r].x += s * wv.x; acc[r].y += s * wv.y;
            acc[r].z += s * wv.z; acc[r].w += s * wv.w;
        }
    }
#pragma unroll
    for (int r = 0; r < 4; r++)
        *(float4*)(w + (size_t)(t0 + r) * 1024 + d) = acc[r];
}

// ---------------- 7. per-channel cumsum of w_h = -exp(w) over t ----------------
__global__ __launch_bounds__(1024) void cumsum_k(const float* __restrict__ w,
                                                 float* __restrict__ cs) {
    __shared__ float seg[32][33];
    int c = threadIdx.x & 31;
    int j = threadIdx.x >> 5;
    int d = blockIdx.x * 32 + c;
    int tb = j * 64;
    float s = 0.f;
    for (int t = 0; t < 64; t++)
        s -= expf(w[(size_t)(tb + t) * 1024 + d]);
    seg[j][c] = s;
    __syncthreads();
    if (j == 0) {
        float run = 0.f;
        for (int jj = 0; jj < 32; jj++) {
            float tmp = seg[jj][c];
            seg[jj][c] = run;
            run += tmp;
        }
    }
    __syncthreads();
    float run = seg[j][c];
    for (int t = 0; t < 64; t++) {
        run -= expf(w[(size_t)(tb + t) * 1024 + d]);
        cs[(size_t)(tb + t) * 1024 + d] = run;
    }
}

// ---------------- 8. exp-premultiplied operands r1,k1,r2,k2 ----------------
__global__ __launch_bounds__(256) void premult_k(const float* __restrict__ r,
                                                 const float* __restrict__ k,
                                                 const float* __restrict__ w,
                                                 const float* __restrict__ cs,
                                                 float* __restrict__ r1,
                                                 float* __restrict__ k1,
                                                 float* __restrict__ r2,
                                                 float* __restrict__ k2) {
    int idx = blockIdx.x * 256 + threadIdx.x;
    if (idx >= TD) return;
    int d = idx & 1023;
    size_t midoff = (size_t)(TTOK / 2) * 1024 + d;  // t = 1024
    float csv = cs[idx];
    float csm = cs[midoff];
    float wh   = -expf(w[idx]);
    float whm  = -expf(w[midoff]);
    float csf = clip60(csv - csm);
    float csb = clip60((csv - wh) - (csm - whm));
    float rv = r[idx], kv = k[idx];
    r1[idx] = rv * expf(csf);
    k1[idx] = kv * expf(-csf);
    r2[idx] = rv * expf(-csb);
    k2[idx] = kv * expf(csb);
}

// ---------------- 9. attention (flash-style, bidirectional, pow sharpening) ----------------
#define ALD 68
__global__ __launch_bounds__(256) void attn_k(const float* __restrict__ r1g,
                                              const float* __restrict__ k1g,
                                              const float* __restrict__ r2g,
                                              const float* __restrict__ k2g,
                                              const float* __restrict__ vg,
                                              const float* __restrict__ log_tau,
                                              float* __restrict__ y) {
    extern __shared__ float sm[];
    float* r1T = sm;
    float* r2T = r1T + 64 * ALD;
    float* k1T = r2T + 64 * ALD;
    float* k2T = k1T + 64 * ALD;
    float* vs  = k2T + 64 * ALD;
    float* aT  = vs  + 64 * ALD;
    __shared__ float redA[64], redS[64];

    int h = blockIdx.y;
    int it = blockIdx.x;
    int t0 = it * 64;
    int tid = threadIdx.x;
    int ty = tid >> 4, tx = tid & 15;
    size_t hb = (size_t)h * 64;
    float tau = expf(log_tau[h]);

    // stage r1/r2 row tiles (transposed: [kk][t])
    for (int i = tid; i < 1024; i += 256) {
        int row = i >> 4;
        int c = (i & 15) * 4;
        size_t off = (size_t)(t0 + row) * 1024 + hb + c;
        float4 a = *(const float4*)(r1g + off);
        r1T[(c + 0) * ALD + row] = a.x; r1T[(c + 1) * ALD + row] = a.y;
        r1T[(c + 2) * ALD + row] = a.z; r1T[(c + 3) * ALD + row] = a.w;
        float4 b = *(const float4*)(r2g + off);
        r2T[(c + 0) * ALD + row] = b.x; r2T[(c + 1) * ALD + row] = b.y;
        r2T[(c + 2) * ALD + row] = b.z; r2T[(c + 3) * ALD + row] = b.w;
    }
    if (tid < 64) { redA[tid] = 0.f; redS[tid] = 0.f; }
    __syncthreads();

    float accY[4][4];
#pragma unroll
    for (int i = 0; i < 4; i++)
#pragma unroll
        for (int j = 0; j < 4; j++) accY[i][j] = 0.f;
    float sumA[4] = {0.f, 0.f, 0.f, 0.f};
    float sumS[4] = {0.f, 0.f, 0.f, 0.f};

    for (int jt = 0; jt < 32; jt++) {
        int s0 = jt * 64;
        bool needF = (jt <= it);
        bool needB = (jt >= it);
        // stage k tiles (transposed) and v tile (row-major)
        for (int i = tid; i < 1024; i += 256) {
            int row = i >> 4;
            int c = (i & 15) * 4;
            size_t off = (size_t)(s0 + row) * 1024 + hb + c;
            if (needF) {
                float4 a = *(const float4*)(k1g + off);
                k1T[(c + 0) * ALD + row] = a.x; k1T[(c + 1) * ALD + row] = a.y;
                k1T[(c + 2) * ALD + row] = a.z; k1T[(c + 3) * ALD + row] = a.w;
            }
            if (needB) {
                float4 a = *(const float4*)(k2g + off);
                k2T[(c + 0) * ALD + row] = a.x; k2T[(c + 1) * ALD + row] = a.y;
                k2T[(c + 2) * ALD + row] = a.z; k2T[(c + 3) * ALD + row] = a.w;
            }
            *(float4*)(vs + row * ALD + c) = *(const float4*)(vg + off);
        }
        __syncthreads();

        float accF[4][4], accB[4][4];
#pragma unroll
        for (int i = 0; i < 4; i++)
#pragma unroll
            for (int j = 0; j < 4; j++) { accF[i][j] = 0.f; accB[i][j] = 0.f; }

        if (needF) {
#pragma unroll 8
            for (int kk = 0; kk < 64; kk++) {
                float av[4], bv[4];
                *(float4*)av = *(const float4*)(r1T + kk * ALD + ty * 4);
                *(float4*)bv = *(const float4*)(k1T + kk * ALD + tx * 4);
#pragma unroll
                for (int i = 0; i < 4; i++)
#pragma unroll
                    for (int j = 0; j < 4; j++) accF[i][j] += av[i] * bv[j];
            }
        }
        if (needB) {
#pragma unroll 8
            for (int kk = 0; kk < 64; kk++) {
                float av[4], bv[4];
                *(float4*)av = *(const float4*)(r2T + kk * ALD + ty * 4);
                *(float4*)bv = *(const float4*)(k2T + kk * ALD + tx * 4);
#pragma unroll
                for (int i = 0; i < 4; i++)
#pragma unroll
                    for (int j = 0; j < 4; j++) accB[i][j] += av[i] * bv[j];
            }
        }
        // elementwise: mask select, relu, pow, row sums; stash ash transposed
#pragma unroll
        for (int i = 0; i < 4; i++) {
            int trow = ty * 4 + i;
#pragma unroll
            for (int j = 0; j < 4; j++) {
                int scol = tx * 4 + j;
                float val;
                if (jt < it) val = accF[i][j];
                else if (jt > it) val = accB[i][j];
                else val = (scol > trow) ? accB[i][j] : accF[i][j];
                float a = fmaxf(val, 0.f);
                sumA[i] += a;
                float ash = (a > 0.f) ? __powf(a + 1e-12f, tau) : 0.f;
                sumS[i] += ash;
                aT[scol * ALD + trow] = ash;
            }
        }
        __syncthreads();
        // accY += Ash @ V
#pragma unroll 8
        for (int s = 0; s < 64; s++) {
            float av[4], bv[4];
            *(float4*)av = *(const float4*)(aT + s * ALD + ty * 4);
            *(float4*)bv = *(const float4*)(vs + s * ALD + tx * 4);
#pragma unroll
            for (int i = 0; i < 4; i++)
#pragma unroll
                for (int j = 0; j < 4; j++) accY[i][j] += av[i] * bv[j];
        }
        __syncthreads();
    }

#pragma unroll
    for (int i = 0; i < 4; i++) {
        atomicAdd(&redA[ty * 4 + i], sumA[i]);
        atomicAdd(&redS[ty * 4 + i], sumS[i]);
    }
    __syncthreads();
#pragma unroll
    for (int i = 0; i < 4; i++) {
        int trow = ty * 4 + i;
        float sc = fmaxf(redA[trow], 1e-12f) / fmaxf(redS[trow], 1e-12f);
        float4 o;
        o.x = accY[i][0] * sc; o.y = accY[i][1] * sc;
        o.z = accY[i][2] * sc; o.w = accY[i][3] * sc;
        *(float4*)(y + (size_t)(t0 + trow) * 1024 + hb + tx * 4) = o;
    }
}

// ---------------- 10. groupnorm per (t, h) + gate ----------------
__global__ __launch_bounds__(256) void gnorm_k(const float* __restrict__ y,
                                               const float* __restrict__ g,
                                               const float* __restrict__ ln_g,
                                               const float* __restrict__ ln_b,
                                               float* __restrict__ yg) {
    int gw = (blockIdx.x * 256 + threadIdx.x) >> 5;
    int lane = threadIdx.x & 31;
    int t = gw >> 4, h = gw & 15;
    size_t off = (size_t)t * 1024 + h * 64 + lane * 2;
    float2 vv = *(const float2*)(y + off);
    float s = vv.x + vv.y;
    float sq = vv.x * vv.x + vv.y * vv.y;
#pragma unroll
    for (int o = 16; o > 0; o >>= 1) {
        s  += __shfl_xor_sync(0xFFFFFFFFu, s, o);
        sq += __shfl_xor_sync(0xFFFFFFFFu, sq, o);
    }
    float mu = s * (1.f / 64.f);
    float var = sq * (1.f / 64.f) - mu * mu;
    float inv = rsqrtf(var + 6.4e-4f);
    int d = h * 64 + lane * 2;
    float2 gg = *(const float2*)(g + (size_t)t * 1024 + d);
    float2 o;
    o.x = ((vv.x - mu) * inv * ln_g[d]     + ln_b[d])     * gg.x;
    o.y = ((vv.y - mu) * inv * ln_g[d + 1] + ln_b[d + 1]) * gg.y;
    *(float2*)(yg + off) = o;
}

// ---------------- launch ----------------
extern "C" void kernel_launch(void* const* d_in, const int* in_sizes, int n_in,
                              void* d_out, int out_size) {
    const float* x          = (const float*)d_in[0];
    const float* maa_x      = (const float*)d_in[1];
    const float* maa_w      = (const float*)d_in[2];
    const float* maa_k      = (const float*)d_in[3];
    const float* maa_v      = (const float*)d_in[4];
    const float* maa_r      = (const float*)d_in[5];
    const float* maa_g      = (const float*)d_in[6];
    const float* maa_w1     = (const float*)d_in[7];
    const float* maa_w2     = (const float*)d_in[8];
    const float* time_decay = (const float*)d_in[9];
    const float* decay_w1   = (const float*)d_in[10];
    const float* decay_w2   = (const float*)d_in[11];
    const float* log_tau    = (const float*)d_in[12];
    const float* Wr         = (const float*)d_in[13];
    const float* Wk         = (const float*)d_in[14];
    const float* Wv         = (const float*)d_in[15];
    const float* Wg         = (const float*)d_in[16];
    const float* Wo         = (const float*)d_in[17];
    const float* ln_g       = (const float*)d_in[18];
    const float* ln_b       = (const float*)d_in[19];

    float* S = nullptr;
    cudaGetSymbolAddress((void**)&S, g_scratch);
    float* dxb   = S + OFF_DX;
    float* zb    = S + OFF_Z;
    float* xwb   = S + OFF_XW;
    float* xproj = S + OFF_XPROJ;
    float* rkvg  = S + OFF_RKVG;
    float* wb    = S + OFF_W;
    float* csb   = S + OFF_CS;
    float* r1b   = S + OFF_R1;
    float* k1b   = S + OFF_K1;
    float* r2b   = S + OFF_R2;
    float* k2b   = S + OFF_K2;
    float* yb    = S + OFF_Y;
    float* ygb   = S + OFF_YG;
    float* xxxb  = S + OFF_XXX;
    float* wmidb = S + OFF_WMID;

    int attn_smem = 6 * 64 * ALD * 4;
    cudaFuncSetAttribute(attn_k, cudaFuncAttributeMaxDynamicSharedMemorySize, attn_smem);

    prep_k<<<(TD + 255) / 256, 256>>>(x, maa_x, dxb, zb);
    xxx_k<<<TTOK / 4, 160>>>(zb, maa_w1, xxxb);
    mix_k<<<TTOK / 4, 256>>>(x, dxb, xxxb, maa_w2,
                             maa_w, maa_k, maa_v, maa_r, maa_g, xwb, xproj);
    {
        dim3 grid(DDIM / 128, TTOK / 128, 4);
        sgemm_k<<<grid, 256>>>(xproj, Wr, Wk, Wv, Wg, rkvg,
                               TTOK, DDIM, DDIM, (size_t)TD, (size_t)TD, 3);
    }
    decay1_k<<<TTOK / 8, 64>>>(xwb, decay_w1, wmidb);
    decay2_k<<<TTOK / 4, 256>>>(wmidb, decay_w2, time_decay, wb);
    cumsum_k<<<DDIM / 32, 1024>>>(wb, csb);
    premult_k<<<(TD + 255) / 256, 256>>>(rkvg, rkvg + (size_t)TD, wb, csb,
                                         r1b, k1b, r2b, k2b);
    {
        dim3 grid(32, 16);
        attn_k<<<grid, 256, attn_smem>>>(r1b, k1b, r2b, k2b,
                                         rkvg + (size_t)2 * TD, log_tau, yb);
    }
    gnorm_k<<<(TTOK * 16) / 8, 256>>>(yb, rkvg + (size_t)3 * TD, ln_g, ln_b, ygb);
    {
        dim3 grid(DDIM / 128, TTOK / 128, 1);
        sgemm_k<<<grid, 256>>>(ygb, Wo, Wo, Wo, Wo, (float*)d_out,
                               TTOK, DDIM, DDIM, (size_t)TD, (size_t)TD, -1);
    }
}

// round 5
// speedup vs baseline: 1.2319x; 1.2319x over previous
#include <cuda_runtime.h>
#include <cuda_bf16.h>
#include <math.h>
#include <stdint.h>

#define TTOK 2048
#define DDIM 1024
#define TD (TTOK*DDIM)

// ---------------- scratch (static device memory; no allocations) ----------------
__device__ float g_scratch[57671680];

#define OFF_DX    ((size_t)0)
#define OFF_Z     ((size_t)TD)
#define OFF_XW    ((size_t)2*TD)
#define OFF_XPROJ ((size_t)3*TD)   // [0]=xr [1]=xk [2]=xv [3]=xg
#define OFF_RKVG  ((size_t)7*TD)   // [0]=r  [1]=k  [2]=v  [3]=g(silu)
#define OFF_W     ((size_t)11*TD)
#define OFF_CS    ((size_t)12*TD)
#define OFF_R1    ((size_t)13*TD)
#define OFF_K1    ((size_t)14*TD)
#define OFF_R2    ((size_t)15*TD)
#define OFF_K2    ((size_t)16*TD)
#define OFF_Y     ((size_t)17*TD)
#define OFF_YG    ((size_t)18*TD)
#define OFF_XXX   ((size_t)19*TD)
#define OFF_WMID  (OFF_XXX + (size_t)TTOK*160)
// bf16 regions (sizes in float units; bf16 count = 2x)
#define OFF_ACTHI ((size_t)20*TD)                 // 4*TD bf16
#define OFF_ACTLO ((size_t)22*TD)                 // 4*TD bf16
#define OFF_WTHI  ((size_t)24*TD)                 // 5*1M bf16
#define OFF_WTLO  (OFF_WTHI + (size_t)2621440)
#define OFF_YGHI  (OFF_WTLO + (size_t)2621440)
#define OFF_YGLO  (OFF_YGHI + (size_t)(TD/2))

static __device__ __forceinline__ float clip60(float x) {
    return fminf(fmaxf(x, -60.f), 60.f);
}
static __device__ __forceinline__ uint32_t smem_u32(const void* p) {
    uint32_t a;
    asm("{ .reg .u64 t; cvta.to.shared.u64 t, %1; cvt.u32.u64 %0, t; }" : "=r"(a) : "l"(p));
    return a;
}

// ---- portable tensor-core primitives (valid at compute_100) ----
#define LDSM_X4(r, addr) \
    asm volatile("ldmatrix.sync.aligned.m8n8.x4.shared.b16 {%0,%1,%2,%3}, [%4];" \
                 : "=r"((r)[0]), "=r"((r)[1]), "=r"((r)[2]), "=r"((r)[3]) : "r"(addr))
#define MMA16816(d, a, b) \
    asm volatile("mma.sync.aligned.m16n8k16.row.col.f32.bf16.bf16.f32 " \
                 "{%0,%1,%2,%3}, {%4,%5,%6,%7}, {%8,%9}, {%0,%1,%2,%3};" \
                 : "+f"((d)[0]), "+f"((d)[1]), "+f"((d)[2]), "+f"((d)[3]) \
                 : "r"((a)[0]), "r"((a)[1]), "r"((a)[2]), "r"((a)[3]), \
                   "r"((b)[0]), "r"((b)[1]))
#define CPASYNC16(s, g) \
    asm volatile("cp.async.cg.shared.global [%0], [%1], 16;" :: "r"(s), "l"(g))
#define CPCOMMIT() asm volatile("cp.async.commit_group;" ::: "memory")
#define CPWAIT1()  asm volatile("cp.async.wait_group 1;" ::: "memory")
#define CPWAIT0()  asm volatile("cp.async.wait_group 0;" ::: "memory")

// ---------------- 1. token shift + z = x + dx*maa_x ----------------
__global__ __launch_bounds__(256) void prep_k(const float* __restrict__ x,
                                              const float* __restrict__ maa_x,
                                              float* __restrict__ dx,
                                              float* __restrict__ z) {
    int idx = blockIdx.x * 256 + threadIdx.x;
    if (idx >= TD) return;
    int t = idx >> 10;
    int d = idx & 1023;
    float xv = x[idx];
    float prev = (t > 0) ? x[idx - 1024] : 0.f;
    float nxt  = (t < TTOK - 1) ? x[idx + 1024] : 0.f;
    float dxv = 0.5f * (prev + nxt) - xv;
    dx[idx] = dxv;
    z[idx]  = xv + dxv * maa_x[d];
}

// ---------------- 2. xxx = tanh(z @ maa_w1)   (2048 x 160) ----------------
__global__ __launch_bounds__(160) void xxx_k(const float* __restrict__ z,
                                             const float* __restrict__ w1,
                                             float* __restrict__ xxx) {
    __shared__ float zs[4][1024];
    int t0 = blockIdx.x * 4;
    int tid = threadIdx.x;
    for (int i = tid; i < 4 * 1024; i += 160) {
        int r = i >> 10, c = i & 1023;
        zs[r][c] = z[(size_t)(t0 + r) * 1024 + c];
    }
    __syncthreads();
    float acc[4] = {0.f, 0.f, 0.f, 0.f};
    for (int d = 0; d < 1024; d++) {
        float w = w1[d * 160 + tid];
        acc[0] += zs[0][d] * w;
        acc[1] += zs[1][d] * w;
        acc[2] += zs[2][d] * w;
        acc[3] += zs[3][d] * w;
    }
#pragma unroll
    for (int r = 0; r < 4; r++)
        xxx[(size_t)(t0 + r) * 160 + tid] = tanhf(acc[r]);
}

// ---------------- 3. mixer ----------------
__global__ __launch_bounds__(256) void mix_k(const float* __restrict__ x,
                                             const float* __restrict__ dx,
                                             const float* __restrict__ xxx,
                                             const float* __restrict__ w2,
                                             const float* __restrict__ maa_w,
                                             const float* __restrict__ maa_k,
                                             const float* __restrict__ maa_v,
                                             const float* __restrict__ maa_r,
                                             const float* __restrict__ maa_g,
                                             float* __restrict__ xw,
                                             float* __restrict__ xproj) {
    __shared__ float xs[4][160];
    int t0 = blockIdx.x * 4;
    int tid = threadIdx.x;
    for (int i = tid; i < 640; i += 256) {
        int r = i / 160, c = i - r * 160;
        xs[r][c] = xxx[(size_t)(t0 + r) * 160 + c];
    }
    __syncthreads();
    int d = tid * 4;
    float4 xv[4], dxv[4];
#pragma unroll
    for (int r = 0; r < 4; r++) {
        xv[r]  = *(const float4*)(x  + (size_t)(t0 + r) * 1024 + d);
        dxv[r] = *(const float4*)(dx + (size_t)(t0 + r) * 1024 + d);
    }
#pragma unroll
    for (int f = 0; f < 5; f++) {
        float4 acc[4];
#pragma unroll
        for (int r = 0; r < 4; r++) acc[r] = make_float4(0.f, 0.f, 0.f, 0.f);
        for (int mi = 0; mi < 32; mi++) {
            float4 w = *(const float4*)(w2 + (size_t)(f * 32 + mi) * 1024 + d);
#pragma unroll
            for (int r = 0; r < 4; r++) {
                float s = xs[r][f * 32 + mi];
                acc[r].x += s * w.x; acc[r].y += s * w.y;
                acc[r].z += s * w.z; acc[r].w += s * w.w;
            }
        }
        const float* maa = (f == 0) ? maa_w : (f == 1) ? maa_k : (f == 2) ? maa_v
                         : (f == 3) ? maa_r : maa_g;
        float4 mv = *(const float4*)(maa + d);
        float* outp;
        if (f == 0)      outp = xw;
        else if (f == 1) outp = xproj + (size_t)1 * TD;
        else if (f == 2) outp = xproj + (size_t)2 * TD;
        else if (f == 3) outp = xproj;
        else             outp = xproj + (size_t)3 * TD;
#pragma unroll
        for (int r = 0; r < 4; r++) {
            float4 o;
            o.x = xv[r].x + dxv[r].x * (mv.x + acc[r].x);
            o.y = xv[r].y + dxv[r].y * (mv.y + acc[r].y);
            o.z = xv[r].z + dxv[r].z * (mv.z + acc[r].z);
            o.w = xv[r].w + dxv[r].w * (mv.w + acc[r].w);
            *(float4*)(outp + (size_t)(t0 + r) * 1024 + d) = o;
        }
    }
}

// ---------------- split fp32 -> bf16 hi/lo ----------------
__global__ __launch_bounds__(256) void conv_split_k(const float* __restrict__ in,
                                                    __nv_bfloat16* __restrict__ hi,
                                                    __nv_bfloat16* __restrict__ lo,
                                                    int n) {
    int idx = blockIdx.x * 256 + threadIdx.x;
    if (idx >= n) return;
    float v = in[idx];
    __nv_bfloat16 h = __float2bfloat16(v);
    hi[idx] = h;
    lo[idx] = __float2bfloat16(v - __bfloat162float(h));
}

// ---------------- weight transpose + split: out[z][n][k] = W_z[k][n] ----------------
__global__ __launch_bounds__(256) void conv_wt_k(const float* __restrict__ W0,
                                                 const float* __restrict__ W1,
                                                 const float* __restrict__ W2,
                                                 const float* __restrict__ W3,
                                                 const float* __restrict__ W4,
                                                 __nv_bfloat16* __restrict__ hi,
                                                 __nv_bfloat16* __restrict__ lo) {
    __shared__ float tile[32][33];
    int z = blockIdx.z;
    const float* W = (z == 0) ? W0 : (z == 1) ? W1 : (z == 2) ? W2 : (z == 3) ? W3 : W4;
    int k0 = blockIdx.x * 32, n0 = blockIdx.y * 32;
    int tx = threadIdx.x & 31, ty = threadIdx.x >> 5;
#pragma unroll
    for (int i = 0; i < 32; i += 8)
        tile[ty + i][tx] = W[(size_t)(k0 + ty + i) * 1024 + n0 + tx];
    __syncthreads();
    size_t base = (size_t)z * 1048576;
#pragma unroll
    for (int i = 0; i < 32; i += 8) {
        float v = tile[tx][ty + i];
        size_t o = base + (size_t)(n0 + ty + i) * 1024 + k0 + tx;
        __nv_bfloat16 h = __float2bfloat16(v);
        hi[o] = h;
        lo[o] = __float2bfloat16(v - __bfloat162float(h));
    }
}

// ---------------- mma.sync split-bf16 GEMM: C[2048,1024] = A @ B^T ----------------
__global__ __launch_bounds__(256, 1)
void gemm_mma_k(const __nv_bfloat16* __restrict__ aHi,
                const __nv_bfloat16* __restrict__ aLo,
                const __nv_bfloat16* __restrict__ bHi,
                const __nv_bfloat16* __restrict__ bLo,
                float* __restrict__ C, int siluZ) {
    extern __shared__ unsigned char smraw[];
    const int tid = threadIdx.x;
    const int z = blockIdx.z;
    const int bm = blockIdx.y * 128;
    const int bn = blockIdx.x * 128;
    const __nv_bfloat16* src_t[4] = {
        aHi + (size_t)z * TD, aLo + (size_t)z * TD,
        bHi + (size_t)z * 1048576, bLo + (size_t)z * 1048576 };
    float* Cz = C + (size_t)z * TD;

    const uint32_t sbase = smem_u32(smraw);
    const int w = tid >> 5, lane = tid & 31;
    const int mw = w >> 1, nw = w & 1;     // 4x2 warp grid

    float acc[2][8][4];
#pragma unroll
    for (int mt = 0; mt < 2; mt++)
#pragma unroll
        for (int nt = 0; nt < 8; nt++)
#pragma unroll
            for (int q = 0; q < 4; q++) acc[mt][nt][q] = 0.f;

    // stage layout: 4 tiles x 16KB (AH, AL, BH, BL), 128 rows x 128B, SW128 swizzle
    auto issue = [&](int c) {
        int buf = c & 1;
        int k0 = c * 64;
#pragma unroll 4
        for (int i = tid; i < 4096; i += 256) {
            int tile = i >> 10;
            int idx = i & 1023;
            int row = idx >> 3, ch = idx & 7;
            int rbase = (tile < 2) ? bm : bn;
            const char* g = (const char*)src_t[tile]
                          + ((size_t)(rbase + row) * 1024 + k0) * 2 + ch * 16;
            uint32_t o = row * 128 + ch * 16;
            o ^= (o >> 3) & 0x70;
            CPASYNC16(sbase + buf * 65536 + tile * 16384 + o, g);
        }
        CPCOMMIT();
    };

    issue(0);
    issue(1);

    for (int c = 0; c < 16; c++) {
        if (c < 15) CPWAIT1(); else CPWAIT0();
        __syncthreads();
        uint32_t st = sbase + (c & 1) * 65536;
#pragma unroll
        for (int kk = 0; kk < 4; kk++) {
            int cb = kk * 2 + (lane >> 4);
            uint32_t ah[2][4], al[2][4];
#pragma unroll
            for (int mt = 0; mt < 2; mt++) {
                int r = mw * 32 + mt * 16 + (lane & 15);
                uint32_t o = r * 128 + cb * 16;
                o ^= (o >> 3) & 0x70;
                LDSM_X4(ah[mt], st + o);
                LDSM_X4(al[mt], st + 16384 + o);
            }
            uint32_t bh[8][2], bl[8][2];
#pragma unroll
            for (int p = 0; p < 4; p++) {
                int r = nw * 64 + p * 16 + (lane & 15);
                uint32_t o = r * 128 + cb * 16;
                o ^= (o >> 3) & 0x70;
                uint32_t t4[4];
                LDSM_X4(t4, st + 32768 + o);
                bh[2 * p][0] = t4[0]; bh[2 * p][1] = t4[2];
                bh[2 * p + 1][0] = t4[1]; bh[2 * p + 1][1] = t4[3];
                LDSM_X4(t4, st + 49152 + o);
                bl[2 * p][0] = t4[0]; bl[2 * p][1] = t4[2];
                bl[2 * p + 1][0] = t4[1]; bl[2 * p + 1][1] = t4[3];
            }
#pragma unroll
            for (int mt = 0; mt < 2; mt++)
#pragma unroll
                for (int nt = 0; nt < 8; nt++) {
                    MMA16816(acc[mt][nt], ah[mt], bh[nt]);
                    MMA16816(acc[mt][nt], ah[mt], bl[nt]);
                    MMA16816(acc[mt][nt], al[mt], bh[nt]);
                }
        }
        __syncthreads();
        if (c + 2 < 16) issue(c + 2);
    }

    // epilogue: fragment -> global (optional silu)
    bool silu = (z == siluZ);
    int r0 = bm + mw * 32, c0 = bn + nw * 64;
#pragma unroll
    for (int mt = 0; mt < 2; mt++)
#pragma unroll
        for (int nt = 0; nt < 8; nt++) {
            float* d = acc[mt][nt];
            if (silu) {
#pragma unroll
                for (int q = 0; q < 4; q++) d[q] = d[q] / (1.f + expf(-d[q]));
            }
            int row = r0 + mt * 16 + (lane >> 2);
            int col = c0 + nt * 8 + (lane & 3) * 2;
            *(float2*)&Cz[(size_t)row * 1024 + col]       = make_float2(d[0], d[1]);
            *(float2*)&Cz[(size_t)(row + 8) * 1024 + col] = make_float2(d[2], d[3]);
        }
}

// ---------------- 5. decay MLP stage 1 ----------------
__global__ __launch_bounds__(64) void decay1_k(const float* __restrict__ xw,
                                               const float* __restrict__ dw1,
                                               float* __restrict__ wmid) {
    __shared__ float xs[8][1024];
    int t0 = blockIdx.x * 8;
    int tid = threadIdx.x;
    for (int i = tid; i < 8 * 256; i += 64) {
        int r = i >> 8;
        int c4 = (i & 255) * 4;
        *(float4*)(&xs[r][c4]) = *(const float4*)(xw + (size_t)(t0 + r) * 1024 + c4);
    }
    __syncthreads();
    float acc[8] = {0.f, 0.f, 0.f, 0.f, 0.f, 0.f, 0.f, 0.f};
    for (int d = 0; d < 1024; d++) {
        float w = dw1[d * 64 + tid];
#pragma unroll
        for (int r = 0; r < 8; r++) acc[r] += xs[r][d] * w;
    }
#pragma unroll
    for (int r = 0; r < 8; r++)
        wmid[(size_t)(t0 + r) * 64 + tid] = tanhf(acc[r]);
}

// ---------------- 6. decay MLP stage 2 ----------------
__global__ __launch_bounds__(256) void decay2_k(const float* __restrict__ wmid,
                                                const float* __restrict__ dw2,
                                                const float* __restrict__ td,
                                                float* __restrict__ w) {
    __shared__ float ws[4][64];
    int t0 = blockIdx.x * 4;
    int tid = threadIdx.x;
    {
        int r = tid >> 6, c = tid & 63;
        ws[r][c] = wmid[(size_t)(t0 + r) * 64 + c];
    }
    __syncthreads();
    int d = tid * 4;
    float4 tdv = *(const float4*)(td + d);
    float4 acc[4];
#pragma unroll
    for (int r = 0; r < 4; r++) acc[r] = tdv;
    for (int j = 0; j < 64; j++) {
        float4 wv = *(const float4*)(dw2 + (size_t)j * 1024 + d);
#pragma unroll
        for (int r = 0; r < 4; r++) {
            float s = ws[r][j];
            acc[r].x += s * wv.x; acc[r].y += s * wv.y;
            acc[r].z += s * wv.z; acc[r].w += s * wv.w;
        }
    }
#pragma unroll
    for (int r = 0; r < 4; r++)
        *(float4*)(w + (size_t)(t0 + r) * 1024 + d) = acc[r];
}

// ---------------- 7. per-channel cumsum ----------------
__global__ __launch_bounds__(1024) void cumsum_k(const float* __restrict__ w,
                                                 float* __restrict__ cs) {
    __shared__ float seg[32][33];
    int c = threadIdx.x & 31;
    int j = threadIdx.x >> 5;
    int d = blockIdx.x * 32 + c;
    int tb = j * 64;
    float s = 0.f;
    for (int t = 0; t < 64; t++)
        s -= expf(w[(size_t)(tb + t) * 1024 + d]);
    seg[j][c] = s;
    __syncthreads();
    if (j == 0) {
        float run = 0.f;
        for (int jj = 0; jj < 32; jj++) {
            float tmp = seg[jj][c];
            seg[jj][c] = run;
            run += tmp;
        }
    }
    __syncthreads();
    float run = seg[j][c];
    for (int t = 0; t < 64; t++) {
        run -= expf(w[(size_t)(tb + t) * 1024 + d]);
        cs[(size_t)(tb + t) * 1024 + d] = run;
    }
}

// ---------------- 8. exp-premultiplied operands ----------------
__global__ __launch_bounds__(256) void premult_k(const float* __restrict__ r,
                                                 const float* __restrict__ k,
                                                 const float* __restrict__ w,
                                                 const float* __restrict__ cs,
                                                 float* __restrict__ r1,
                                                 float* __restrict__ k1,
                                                 float* __restrict__ r2,
                                                 float* __restrict__ k2) {
    int idx = blockIdx.x * 256 + threadIdx.x;
    if (idx >= TD) return;
    int d = idx & 1023;
    size_t midoff = (size_t)(TTOK / 2) * 1024 + d;
    float csv = cs[idx];
    float csm = cs[midoff];
    float wh   = -expf(w[idx]);
    float whm  = -expf(w[midoff]);
    float csf = clip60(csv - csm);
    float csb = clip60((csv - wh) - (csm - whm));
    float rv = r[idx], kv = k[idx];
    r1[idx] = rv * expf(csf);
    k1[idx] = kv * expf(-csf);
    r2[idx] = rv * expf(-csb);
    k2[idx] = kv * expf(csb);
}

// ---------------- 9. attention (flash-style, bidirectional, pow sharpening) ----------------
#define ALD 68
__global__ __launch_bounds__(256) void attn_k(const float* __restrict__ r1g,
                                              const float* __restrict__ k1g,
                                              const float* __restrict__ r2g,
                                              const float* __restrict__ k2g,
                                              const float* __restrict__ vg,
                                              const float* __restrict__ log_tau,
                                              float* __restrict__ y) {
    extern __shared__ float sm[];
    float* r1T = sm;
    float* r2T = r1T + 64 * ALD;
    float* k1T = r2T + 64 * ALD;
    float* k2T = k1T + 64 * ALD;
    float* vs  = k2T + 64 * ALD;
    float* aT  = vs  + 64 * ALD;
    __shared__ float redA[64], redS[64];

    int h = blockIdx.y;
    int it = blockIdx.x;
    int t0 = it * 64;
    int tid = threadIdx.x;
    int ty = tid >> 4, tx = tid & 15;
    size_t hb = (size_t)h * 64;
    float tau = expf(log_tau[h]);

    for (int i = tid; i < 1024; i += 256) {
        int row = i >> 4;
        int c = (i & 15) * 4;
        size_t off = (size_t)(t0 + row) * 1024 + hb + c;
        float4 a = *(const float4*)(r1g + off);
        r1T[(c + 0) * ALD + row] = a.x; r1T[(c + 1) * ALD + row] = a.y;
        r1T[(c + 2) * ALD + row] = a.z; r1T[(c + 3) * ALD + row] = a.w;
        float4 b = *(const float4*)(r2g + off);
        r2T[(c + 0) * ALD + row] = b.x; r2T[(c + 1) * ALD + row] = b.y;
        r2T[(c + 2) * ALD + row] = b.z; r2T[(c + 3) * ALD + row] = b.w;
    }
    if (tid < 64) { redA[tid] = 0.f; redS[tid] = 0.f; }
    __syncthreads();

    float accY[4][4];
#pragma unroll
    for (int i = 0; i < 4; i++)
#pragma unroll
        for (int j = 0; j < 4; j++) accY[i][j] = 0.f;
    float sumA[4] = {0.f, 0.f, 0.f, 0.f};
    float sumS[4] = {0.f, 0.f, 0.f, 0.f};

    for (int jt = 0; jt < 32; jt++) {
        int s0 = jt * 64;
        bool needF = (jt <= it);
        bool needB = (jt >= it);
        for (int i = tid; i < 1024; i += 256) {
            int row = i >> 4;
            int c = (i & 15) * 4;
            size_t off = (size_t)(s0 + row) * 1024 + hb + c;
            if (needF) {
                float4 a = *(const float4*)(k1g + off);
                k1T[(c + 0) * ALD + row] = a.x; k1T[(c + 1) * ALD + row] = a.y;
                k1T[(c + 2) * ALD + row] = a.z; k1T[(c + 3) * ALD + row] = a.w;
            }
            if (needB) {
                float4 a = *(const float4*)(k2g + off);
                k2T[(c + 0) * ALD + row] = a.x; k2T[(c + 1) * ALD + row] = a.y;
                k2T[(c + 2) * ALD + row] = a.z; k2T[(c + 3) * ALD + row] = a.w;
            }
            *(float4*)(vs + row * ALD + c) = *(const float4*)(vg + off);
        }
        __syncthreads();

        float accF[4][4], accB[4][4];
#pragma unroll
        for (int i = 0; i < 4; i++)
#pragma unroll
            for (int j = 0; j < 4; j++) { accF[i][j] = 0.f; accB[i][j] = 0.f; }

        if (needF) {
#pragma unroll 8
            for (int kk = 0; kk < 64; kk++) {
                float av[4], bv[4];
                *(float4*)av = *(const float4*)(r1T + kk * ALD + ty * 4);
                *(float4*)bv = *(const float4*)(k1T + kk * ALD + tx * 4);
#pragma unroll
                for (int i = 0; i < 4; i++)
#pragma unroll
                    for (int j = 0; j < 4; j++) accF[i][j] += av[i] * bv[j];
            }
        }
        if (needB) {
#pragma unroll 8
            for (int kk = 0; kk < 64; kk++) {
                float av[4], bv[4];
                *(float4*)av = *(const float4*)(r2T + kk * ALD + ty * 4);
                *(float4*)bv = *(const float4*)(k2T + kk * ALD + tx * 4);
#pragma unroll
                for (int i = 0; i < 4; i++)
#pragma unroll
                    for (int j = 0; j < 4; j++) accB[i][j] += av[i] * bv[j];
            }
        }
#pragma unroll
        for (int i = 0; i < 4; i++) {
            int trow = ty * 4 + i;
#pragma unroll
            for (int j = 0; j < 4; j++) {
                int scol = tx * 4 + j;
                float val;
                if (jt < it) val = accF[i][j];
                else if (jt > it) val = accB[i][j];
                else val = (scol > trow) ? accB[i][j] : accF[i][j];
                float a = fmaxf(val, 0.f);
                sumA[i] += a;
                float ash = (a > 0.f) ? __powf(a + 1e-12f, tau) : 0.f;
                sumS[i] += ash;
                aT[scol * ALD + trow] = ash;
            }
        }
        __syncthreads();
#pragma unroll 8
        for (int s = 0; s < 64; s++) {
            float av[4], bv[4];
            *(float4*)av = *(const float4*)(aT + s * ALD + ty * 4);
            *(float4*)bv = *(const float4*)(vs + s * ALD + tx * 4);
#pragma unroll
            for (int i = 0; i < 4; i++)
#pragma unroll
                for (int j = 0; j < 4; j++) accY[i][j] += av[i] * bv[j];
        }
        __syncthreads();
    }

#pragma unroll
    for (int i = 0; i < 4; i++) {
        atomicAdd(&redA[ty * 4 + i], sumA[i]);
        atomicAdd(&redS[ty * 4 + i], sumS[i]);
    }
    __syncthreads();
#pragma unroll
    for (int i = 0; i < 4; i++) {
        int trow = ty * 4 + i;
        float sc = fmaxf(redA[trow], 1e-12f) / fmaxf(redS[trow], 1e-12f);
        float4 o;
        o.x = accY[i][0] * sc; o.y = accY[i][1] * sc;
        o.z = accY[i][2] * sc; o.w = accY[i][3] * sc;
        *(float4*)(y + (size_t)(t0 + trow) * 1024 + hb + tx * 4) = o;
    }
}

// ---------------- 10. groupnorm per (t, h) + gate ----------------
__global__ __launch_bounds__(256) void gnorm_k(const float* __restrict__ y,
                                               const float* __restrict__ g,
                                               const float* __restrict__ ln_g,
                                               const float* __restrict__ ln_b,
                                               float* __restrict__ yg) {
    int gw = (blockIdx.x * 256 + threadIdx.x) >> 5;
    int lane = threadIdx.x & 31;
    int t = gw >> 4, h = gw & 15;
    size_t off = (size_t)t * 1024 + h * 64 + lane * 2;
    float2 vv = *(const float2*)(y + off);
    float s = vv.x + vv.y;
    float sq = vv.x * vv.x + vv.y * vv.y;
#pragma unroll
    for (int o = 16; o > 0; o >>= 1) {
        s  += __shfl_xor_sync(0xFFFFFFFFu, s, o);
        sq += __shfl_xor_sync(0xFFFFFFFFu, sq, o);
    }
    float mu = s * (1.f / 64.f);
    float var = sq * (1.f / 64.f) - mu * mu;
    float inv = rsqrtf(var + 6.4e-4f);
    int d = h * 64 + lane * 2;
    float2 gg = *(const float2*)(g + (size_t)t * 1024 + d);
    float2 o;
    o.x = ((vv.x - mu) * inv * ln_g[d]     + ln_b[d])     * gg.x;
    o.y = ((vv.y - mu) * inv * ln_g[d + 1] + ln_b[d + 1]) * gg.y;
    *(float2*)(yg + off) = o;
}

// ---------------- launch ----------------
extern "C" void kernel_launch(void* const* d_in, const int* in_sizes, int n_in,
                              void* d_out, int out_size) {
    const float* x          = (const float*)d_in[0];
    const float* maa_x      = (const float*)d_in[1];
    const float* maa_w      = (const float*)d_in[2];
    const float* maa_k      = (const float*)d_in[3];
    const float* maa_v      = (const float*)d_in[4];
    const float* maa_r      = (const float*)d_in[5];
    const float* maa_g      = (const float*)d_in[6];
    const float* maa_w1     = (const float*)d_in[7];
    const float* maa_w2     = (const float*)d_in[8];
    const float* time_decay = (const float*)d_in[9];
    const float* decay_w1   = (const float*)d_in[10];
    const float* decay_w2   = (const float*)d_in[11];
    const float* log_tau    = (const float*)d_in[12];
    const float* Wr         = (const float*)d_in[13];
    const float* Wk         = (const float*)d_in[14];
    const float* Wv         = (const float*)d_in[15];
    const float* Wg         = (const float*)d_in[16];
    const float* Wo         = (const float*)d_in[17];
    const float* ln_g       = (const float*)d_in[18];
    const float* ln_b       = (const float*)d_in[19];

    float* S = nullptr;
    cudaGetSymbolAddress((void**)&S, g_scratch);
    float* dxb   = S + OFF_DX;
    float* zb    = S + OFF_Z;
    float* xwb   = S + OFF_XW;
    float* xproj = S + OFF_XPROJ;
    float* rkvg  = S + OFF_RKVG;
    float* wb    = S + OFF_W;
    float* csb   = S + OFF_CS;
    float* r1b   = S + OFF_R1;
    float* k1b   = S + OFF_K1;
    float* r2b   = S + OFF_R2;
    float* k2b   = S + OFF_K2;
    float* yb    = S + OFF_Y;
    float* ygb   = S + OFF_YG;
    float* xxxb  = S + OFF_XXX;
    float* wmidb = S + OFF_WMID;
    __nv_bfloat16* actHi = (__nv_bfloat16*)(S + OFF_ACTHI);
    __nv_bfloat16* actLo = (__nv_bfloat16*)(S + OFF_ACTLO);
    __nv_bfloat16* wtHi  = (__nv_bfloat16*)(S + OFF_WTHI);
    __nv_bfloat16* wtLo  = (__nv_bfloat16*)(S + OFF_WTLO);
    __nv_bfloat16* ygHi  = (__nv_bfloat16*)(S + OFF_YGHI);
    __nv_bfloat16* ygLo  = (__nv_bfloat16*)(S + OFF_YGLO);

    int attn_smem = 6 * 64 * ALD * 4;
    cudaFuncSetAttribute(attn_k, cudaFuncAttributeMaxDynamicSharedMemorySize, attn_smem);
    int gemm_smem = 131072;
    cudaFuncSetAttribute(gemm_mma_k, cudaFuncAttributeMaxDynamicSharedMemorySize, gemm_smem);

    prep_k<<<(TD + 255) / 256, 256>>>(x, maa_x, dxb, zb);
    xxx_k<<<TTOK / 4, 160>>>(zb, maa_w1, xxxb);
    mix_k<<<TTOK / 4, 256>>>(x, dxb, xxxb, maa_w2,
                             maa_w, maa_k, maa_v, maa_r, maa_g, xwb, xproj);
    conv_split_k<<<(4 * TD + 255) / 256, 256>>>(xproj, actHi, actLo, 4 * TD);
    {
        dim3 grid(32, 32, 5);
        conv_wt_k<<<grid, 256>>>(Wr, Wk, Wv, Wg, Wo, wtHi, wtLo);
    }
    {
        dim3 grid(8, 16, 4);
        gemm_mma_k<<<grid, 256, gemm_smem>>>(actHi, actLo, wtHi, wtLo, rkvg, 3);
    }
    decay1_k<<<TTOK / 8, 64>>>(xwb, decay_w1, wmidb);
    decay2_k<<<TTOK / 4, 256>>>(wmidb, decay_w2, time_decay, wb);
    cumsum_k<<<DDIM / 32, 1024>>>(wb, csb);
    premult_k<<<(TD + 255) / 256, 256>>>(rkvg, rkvg + (size_t)TD, wb, csb,
                                         r1b, k1b, r2b, k2b);
    {
        dim3 grid(32, 16);
        attn_k<<<grid, 256, attn_smem>>>(r1b, k1b, r2b, k2b,
                                         rkvg + (size_t)2 * TD, log_tau, yb);
    }
    gnorm_k<<<(TTOK * 16) / 8, 256>>>(yb, rkvg + (size_t)3 * TD, ln_g, ln_b, ygb);
    conv_split_k<<<(TD + 255) / 256, 256>>>(ygb, ygHi, ygLo, TD);
    {
        dim3 grid(8, 16, 1);
        gemm_mma_k<<<grid, 256, gemm_smem>>>(ygHi, ygLo, wtHi + (size_t)4 * 1048576,
                                             wtLo + (size_t)4 * 1048576,
                                             (float*)d_out, -1);
    }
}

// round 6
// speedup vs baseline: 1.7044x; 1.3836x over previous
#include <cuda_runtime.h>
#include <cuda_bf16.h>
#include <math.h>
#include <stdint.h>

#define TTOK 2048
#define DDIM 1024
#define TD (TTOK*DDIM)

// ---------------- scratch (static device memory; no allocations) ----------------
__device__ float g_scratch[68157440];

#define OFF_DX    ((size_t)0)
#define OFF_Z     ((size_t)TD)
#define OFF_XW    ((size_t)2*TD)
#define OFF_XPROJ ((size_t)3*TD)   // [0]=xr [1]=xk [2]=xv [3]=xg
#define OFF_RKVG  ((size_t)7*TD)   // [0]=r  [1]=k  [2]=v  [3]=g(silu)
#define OFF_W     ((size_t)11*TD)
#define OFF_CS    ((size_t)12*TD)
#define OFF_Y     ((size_t)17*TD)
#define OFF_YG    ((size_t)18*TD)
#define OFF_XXX   ((size_t)19*TD)
#define OFF_WMID  (OFF_XXX + (size_t)TTOK*160)
// bf16 regions (sizes in float units; bf16 count = 2x)
#define OFF_ACTHI ((size_t)20*TD)                 // 4*TD bf16
#define OFF_ACTLO ((size_t)22*TD)                 // 4*TD bf16
#define OFF_WTHI  ((size_t)24*TD)                 // 5*1M bf16
#define OFF_WTLO  (OFF_WTHI + (size_t)2621440)
#define OFF_YGHI  (OFF_WTLO + (size_t)2621440)
#define OFF_YGLO  (OFF_YGHI + (size_t)(TD/2))
// attention bf16 operand arrays: 10 arrays x TD bf16 elems
// order: 0=r1h 1=r1l 2=k1h 3=k1l 4=r2h 5=r2l 6=k2h 7=k2l 8=vh 9=vl
#define OFF_BF    (OFF_YGLO + (size_t)(TD/2))

static __device__ __forceinline__ float clip60(float x) {
    return fminf(fmaxf(x, -60.f), 60.f);
}
static __device__ __forceinline__ uint32_t smem_u32(const void* p) {
    uint32_t a;
    asm("{ .reg .u64 t; cvta.to.shared.u64 t, %1; cvt.u32.u64 %0, t; }" : "=r"(a) : "l"(p));
    return a;
}

// ---- portable tensor-core primitives (valid at compute_100) ----
#define LDSM_X4(r, addr) \
    asm volatile("ldmatrix.sync.aligned.m8n8.x4.shared.b16 {%0,%1,%2,%3}, [%4];" \
                 : "=r"((r)[0]), "=r"((r)[1]), "=r"((r)[2]), "=r"((r)[3]) : "r"(addr))
#define LDSM_X4_T(r, addr) \
    asm volatile("ldmatrix.sync.aligned.m8n8.x4.trans.shared.b16 {%0,%1,%2,%3}, [%4];" \
                 : "=r"((r)[0]), "=r"((r)[1]), "=r"((r)[2]), "=r"((r)[3]) : "r"(addr))
#define MMA16816(d, a, b) \
    asm volatile("mma.sync.aligned.m16n8k16.row.col.f32.bf16.bf16.f32 " \
                 "{%0,%1,%2,%3}, {%4,%5,%6,%7}, {%8,%9}, {%0,%1,%2,%3};" \
                 : "+f"((d)[0]), "+f"((d)[1]), "+f"((d)[2]), "+f"((d)[3]) \
                 : "r"((a)[0]), "r"((a)[1]), "r"((a)[2]), "r"((a)[3]), \
                   "r"((b)[0]), "r"((b)[1]))
#define CPASYNC16(s, g) \
    asm volatile("cp.async.cg.shared.global [%0], [%1], 16;" :: "r"(s), "l"(g))
#define CPCOMMIT() asm volatile("cp.async.commit_group;" ::: "memory")
#define CPWAIT1()  asm volatile("cp.async.wait_group 1;" ::: "memory")
#define CPWAIT0()  asm volatile("cp.async.wait_group 0;" ::: "memory")
#define SWZ(o) ((o) ^ (((o) >> 3) & 0x70))

// ---------------- 1. token shift + z ----------------
__global__ __launch_bounds__(256) void prep_k(const float* __restrict__ x,
                                              const float* __restrict__ maa_x,
                                              float* __restrict__ dx,
                                              float* __restrict__ z) {
    int idx = blockIdx.x * 256 + threadIdx.x;
    if (idx >= TD) return;
    int t = idx >> 10;
    int d = idx & 1023;
    float xv = x[idx];
    float prev = (t > 0) ? x[idx - 1024] : 0.f;
    float nxt  = (t < TTOK - 1) ? x[idx + 1024] : 0.f;
    float dxv = 0.5f * (prev + nxt) - xv;
    dx[idx] = dxv;
    z[idx]  = xv + dxv * maa_x[d];
}

// ---------------- 2. xxx = tanh(z @ maa_w1) ----------------
__global__ __launch_bounds__(160) void xxx_k(const float* __restrict__ z,
                                             const float* __restrict__ w1,
                                             float* __restrict__ xxx) {
    __shared__ float zs[4][1024];
    int t0 = blockIdx.x * 4;
    int tid = threadIdx.x;
    for (int i = tid; i < 4 * 1024; i += 160) {
        int r = i >> 10, c = i & 1023;
        zs[r][c] = z[(size_t)(t0 + r) * 1024 + c];
    }
    __syncthreads();
    float acc[4] = {0.f, 0.f, 0.f, 0.f};
    for (int d = 0; d < 1024; d++) {
        float w = w1[d * 160 + tid];
        acc[0] += zs[0][d] * w;
        acc[1] += zs[1][d] * w;
        acc[2] += zs[2][d] * w;
        acc[3] += zs[3][d] * w;
    }
#pragma unroll
    for (int r = 0; r < 4; r++)
        xxx[(size_t)(t0 + r) * 160 + tid] = tanhf(acc[r]);
}

// ---------------- 3. mixer ----------------
__global__ __launch_bounds__(256) void mix_k(const float* __restrict__ x,
                                             const float* __restrict__ dx,
                                             const float* __restrict__ xxx,
                                             const float* __restrict__ w2,
                                             const float* __restrict__ maa_w,
                                             const float* __restrict__ maa_k,
                                             const float* __restrict__ maa_v,
                                             const float* __restrict__ maa_r,
                                             const float* __restrict__ maa_g,
                                             float* __restrict__ xw,
                                             float* __restrict__ xproj) {
    __shared__ float xs[4][160];
    int t0 = blockIdx.x * 4;
    int tid = threadIdx.x;
    for (int i = tid; i < 640; i += 256) {
        int r = i / 160, c = i - r * 160;
        xs[r][c] = xxx[(size_t)(t0 + r) * 160 + c];
    }
    __syncthreads();
    int d = tid * 4;
    float4 xv[4], dxv[4];
#pragma unroll
    for (int r = 0; r < 4; r++) {
        xv[r]  = *(const float4*)(x  + (size_t)(t0 + r) * 1024 + d);
        dxv[r] = *(const float4*)(dx + (size_t)(t0 + r) * 1024 + d);
    }
#pragma unroll
    for (int f = 0; f < 5; f++) {
        float4 acc[4];
#pragma unroll
        for (int r = 0; r < 4; r++) acc[r] = make_float4(0.f, 0.f, 0.f, 0.f);
        for (int mi = 0; mi < 32; mi++) {
            float4 w = *(const float4*)(w2 + (size_t)(f * 32 + mi) * 1024 + d);
#pragma unroll
            for (int r = 0; r < 4; r++) {
                float s = xs[r][f * 32 + mi];
                acc[r].x += s * w.x; acc[r].y += s * w.y;
                acc[r].z += s * w.z; acc[r].w += s * w.w;
            }
        }
        const float* maa = (f == 0) ? maa_w : (f == 1) ? maa_k : (f == 2) ? maa_v
                         : (f == 3) ? maa_r : maa_g;
        float4 mv = *(const float4*)(maa + d);
        float* outp;
        if (f == 0)      outp = xw;
        else if (f == 1) outp = xproj + (size_t)1 * TD;
        else if (f == 2) outp = xproj + (size_t)2 * TD;
        else if (f == 3) outp = xproj;
        else             outp = xproj + (size_t)3 * TD;
#pragma unroll
        for (int r = 0; r < 4; r++) {
            float4 o;
            o.x = xv[r].x + dxv[r].x * (mv.x + acc[r].x);
            o.y = xv[r].y + dxv[r].y * (mv.y + acc[r].y);
            o.z = xv[r].z + dxv[r].z * (mv.z + acc[r].z);
            o.w = xv[r].w + dxv[r].w * (mv.w + acc[r].w);
            *(float4*)(outp + (size_t)(t0 + r) * 1024 + d) = o;
        }
    }
}

// ---------------- split fp32 -> bf16 hi/lo ----------------
__global__ __launch_bounds__(256) void conv_split_k(const float* __restrict__ in,
                                                    __nv_bfloat16* __restrict__ hi,
                                                    __nv_bfloat16* __restrict__ lo,
                                                    int n) {
    int idx = blockIdx.x * 256 + threadIdx.x;
    if (idx >= n) return;
    float v = in[idx];
    __nv_bfloat16 h = __float2bfloat16(v);
    hi[idx] = h;
    lo[idx] = __float2bfloat16(v - __bfloat162float(h));
}

// ---------------- weight transpose + split ----------------
__global__ __launch_bounds__(256) void conv_wt_k(const float* __restrict__ W0,
                                                 const float* __restrict__ W1,
                                                 const float* __restrict__ W2,
                                                 const float* __restrict__ W3,
                                                 const float* __restrict__ W4,
                                                 __nv_bfloat16* __restrict__ hi,
                                                 __nv_bfloat16* __restrict__ lo) {
    __shared__ float tile[32][33];
    int z = blockIdx.z;
    const float* W = (z == 0) ? W0 : (z == 1) ? W1 : (z == 2) ? W2 : (z == 3) ? W3 : W4;
    int k0 = blockIdx.x * 32, n0 = blockIdx.y * 32;
    int tx = threadIdx.x & 31, ty = threadIdx.x >> 5;
#pragma unroll
    for (int i = 0; i < 32; i += 8)
        tile[ty + i][tx] = W[(size_t)(k0 + ty + i) * 1024 + n0 + tx];
    __syncthreads();
    size_t base = (size_t)z * 1048576;
#pragma unroll
    for (int i = 0; i < 32; i += 8) {
        float v = tile[tx][ty + i];
        size_t o = base + (size_t)(n0 + ty + i) * 1024 + k0 + tx;
        __nv_bfloat16 h = __float2bfloat16(v);
        hi[o] = h;
        lo[o] = __float2bfloat16(v - __bfloat162float(h));
    }
}

// ---------------- mma.sync split-bf16 GEMM (projections / Wo) ----------------
__global__ __launch_bounds__(256, 1)
void gemm_mma_k(const __nv_bfloat16* __restrict__ aHi,
                const __nv_bfloat16* __restrict__ aLo,
                const __nv_bfloat16* __restrict__ bHi,
                const __nv_bfloat16* __restrict__ bLo,
                float* __restrict__ C, int siluZ) {
    extern __shared__ unsigned char smraw[];
    const int tid = threadIdx.x;
    const int z = blockIdx.z;
    const int bm = blockIdx.y * 128;
    const int bn = blockIdx.x * 128;
    const __nv_bfloat16* src_t[4] = {
        aHi + (size_t)z * TD, aLo + (size_t)z * TD,
        bHi + (size_t)z * 1048576, bLo + (size_t)z * 1048576 };
    float* Cz = C + (size_t)z * TD;

    const uint32_t sbase = smem_u32(smraw);
    const int w = tid >> 5, lane = tid & 31;
    const int mw = w >> 1, nw = w & 1;

    float acc[2][8][4];
#pragma unroll
    for (int mt = 0; mt < 2; mt++)
#pragma unroll
        for (int nt = 0; nt < 8; nt++)
#pragma unroll
            for (int q = 0; q < 4; q++) acc[mt][nt][q] = 0.f;

    auto issue = [&](int c) {
        int buf = c & 1;
        int k0 = c * 64;
#pragma unroll 4
        for (int i = tid; i < 4096; i += 256) {
            int tile = i >> 10;
            int idx = i & 1023;
            int row = idx >> 3, ch = idx & 7;
            int rbase = (tile < 2) ? bm : bn;
            const char* g = (const char*)src_t[tile]
                          + ((size_t)(rbase + row) * 1024 + k0) * 2 + ch * 16;
            uint32_t o = SWZ(row * 128 + ch * 16);
            CPASYNC16(sbase + buf * 65536 + tile * 16384 + o, g);
        }
        CPCOMMIT();
    };

    issue(0);
    issue(1);

    for (int c = 0; c < 16; c++) {
        if (c < 15) CPWAIT1(); else CPWAIT0();
        __syncthreads();
        uint32_t st = sbase + (c & 1) * 65536;
#pragma unroll
        for (int kk = 0; kk < 4; kk++) {
            int cb = kk * 2 + (lane >> 4);
            uint32_t ah[2][4], al[2][4];
#pragma unroll
            for (int mt = 0; mt < 2; mt++) {
                int r = mw * 32 + mt * 16 + (lane & 15);
                uint32_t o = SWZ(r * 128 + cb * 16);
                LDSM_X4(ah[mt], st + o);
                LDSM_X4(al[mt], st + 16384 + o);
            }
            uint32_t bh[8][2], bl[8][2];
#pragma unroll
            for (int p = 0; p < 4; p++) {
                int r = nw * 64 + p * 16 + (lane & 15);
                uint32_t o = SWZ(r * 128 + cb * 16);
                uint32_t t4[4];
                LDSM_X4(t4, st + 32768 + o);
                bh[2 * p][0] = t4[0]; bh[2 * p][1] = t4[2];
                bh[2 * p + 1][0] = t4[1]; bh[2 * p + 1][1] = t4[3];
                LDSM_X4(t4, st + 49152 + o);
                bl[2 * p][0] = t4[0]; bl[2 * p][1] = t4[2];
                bl[2 * p + 1][0] = t4[1]; bl[2 * p + 1][1] = t4[3];
            }
#pragma unroll
            for (int mt = 0; mt < 2; mt++)
#pragma unroll
                for (int nt = 0; nt < 8; nt++) {
                    MMA16816(acc[mt][nt], ah[mt], bh[nt]);
                    MMA16816(acc[mt][nt], ah[mt], bl[nt]);
                    MMA16816(acc[mt][nt], al[mt], bh[nt]);
                }
        }
        __syncthreads();
        if (c + 2 < 16) issue(c + 2);
    }

    bool silu = (z == siluZ);
    int r0 = bm + mw * 32, c0 = bn + nw * 64;
#pragma unroll
    for (int mt = 0; mt < 2; mt++)
#pragma unroll
        for (int nt = 0; nt < 8; nt++) {
            float* d = acc[mt][nt];
            if (silu) {
#pragma unroll
                for (int q = 0; q < 4; q++) d[q] = d[q] / (1.f + expf(-d[q]));
            }
            int row = r0 + mt * 16 + (lane >> 2);
            int col = c0 + nt * 8 + (lane & 3) * 2;
            *(float2*)&Cz[(size_t)row * 1024 + col]       = make_float2(d[0], d[1]);
            *(float2*)&Cz[(size_t)(row + 8) * 1024 + col] = make_float2(d[2], d[3]);
        }
}

// ---------------- 5. decay MLP stage 1 ----------------
__global__ __launch_bounds__(64) void decay1_k(const float* __restrict__ xw,
                                               const float* __restrict__ dw1,
                                               float* __restrict__ wmid) {
    __shared__ float xs[8][1024];
    int t0 = blockIdx.x * 8;
    int tid = threadIdx.x;
    for (int i = tid; i < 8 * 256; i += 64) {
        int r = i >> 8;
        int c4 = (i & 255) * 4;
        *(float4*)(&xs[r][c4]) = *(const float4*)(xw + (size_t)(t0 + r) * 1024 + c4);
    }
    __syncthreads();
    float acc[8] = {0.f, 0.f, 0.f, 0.f, 0.f, 0.f, 0.f, 0.f};
    for (int d = 0; d < 1024; d++) {
        float w = dw1[d * 64 + tid];
#pragma unroll
        for (int r = 0; r < 8; r++) acc[r] += xs[r][d] * w;
    }
#pragma unroll
    for (int r = 0; r < 8; r++)
        wmid[(size_t)(t0 + r) * 64 + tid] = tanhf(acc[r]);
}

// ---------------- 6. decay MLP stage 2 ----------------
__global__ __launch_bounds__(256) void decay2_k(const float* __restrict__ wmid,
                                                const float* __restrict__ dw2,
                                                const float* __restrict__ td,
                                                float* __restrict__ w) {
    __shared__ float ws[4][64];
    int t0 = blockIdx.x * 4;
    int tid = threadIdx.x;
    {
        int r = tid >> 6, c = tid & 63;
        ws[r][c] = wmid[(size_t)(t0 + r) * 64 + c];
    }
    __syncthreads();
    int d = tid * 4;
    float4 tdv = *(const float4*)(td + d);
    float4 acc[4];
#pragma unroll
    for (int r = 0; r < 4; r++) acc[r] = tdv;
    for (int j = 0; j < 64; j++) {
        float4 wv = *(const float4*)(dw2 + (size_t)j * 1024 + d);
#pragma unroll
        for (int r = 0; r < 4; r++) {
            float s = ws[r][j];
            acc[r].x += s * wv.x; acc[r].y += s * wv.y;
            acc[r].z += s * wv.z; acc[r].w += s * wv.w;
        }
    }
#pragma unroll
    for (int r = 0; r < 4; r++)
        *(float4*)(w + (size_t)(t0 + r) * 1024 + d) = acc[r];
}

// ---------------- 7. per-channel cumsum ----------------
__global__ __launch_bounds__(1024) void cumsum_k(const float* __restrict__ w,
                                                 float* __restrict__ cs) {
    __shared__ float seg[32][33];
    int c = threadIdx.x & 31;
    int j = threadIdx.x >> 5;
    int d = blockIdx.x * 32 + c;
    int tb = j * 64;
    float s = 0.f;
    for (int t = 0; t < 64; t++)
        s -= expf(w[(size_t)(tb + t) * 1024 + d]);
    seg[j][c] = s;
    __syncthreads();
    if (j == 0) {
        float run = 0.f;
        for (int jj = 0; jj < 32; jj++) {
            float tmp = seg[jj][c];
            seg[jj][c] = run;
            run += tmp;
        }
    }
    __syncthreads();
    float run = seg[j][c];
    for (int t = 0; t < 64; t++) {
        run -= expf(w[(size_t)(tb + t) * 1024 + d]);
        cs[(size_t)(tb + t) * 1024 + d] = run;
    }
}

// ---------------- 8. premult: emit r1/k1/r2/k2 as bf16 hi/lo ----------------
__global__ __launch_bounds__(256) void premult_bf_k(const float* __restrict__ r,
                                                    const float* __restrict__ k,
                                                    const float* __restrict__ w,
                                                    const float* __restrict__ cs,
                                                    __nv_bfloat16* __restrict__ bfB) {
    int idx = blockIdx.x * 256 + threadIdx.x;
    if (idx >= TD) return;
    int d = idx & 1023;
    size_t midoff = (size_t)(TTOK / 2) * 1024 + d;
    float csv = cs[idx];
    float csm = cs[midoff];
    float wh   = -expf(w[idx]);
    float whm  = -expf(w[midoff]);
    float csf = clip60(csv - csm);
    float csb = clip60((csv - wh) - (csm - whm));
    float rv = r[idx], kv = k[idx];
    float vals[4];
    vals[0] = rv * expf(csf);    // r1
    vals[1] = kv * expf(-csf);   // k1
    vals[2] = rv * expf(-csb);   // r2
    vals[3] = kv * expf(csb);    // k2
    // array slots: r1->0/1, k1->2/3, r2->4/5, k2->6/7
#pragma unroll
    for (int j = 0; j < 4; j++) {
        __nv_bfloat16 h = __float2bfloat16(vals[j]);
        bfB[(size_t)(2 * j) * TD + idx] = h;
        bfB[(size_t)(2 * j + 1) * TD + idx] = __float2bfloat16(vals[j] - __bfloat162float(h));
    }
}

// ---------------- 9. attention: mma.sync split-bf16, bidirectional + pow ----------------
// smem layout (bytes): R1H 0, R1L 8K, R2H 16K, R2L 24K,
//                      K1H 32K, K1L 40K, K2H 48K, K2L 56K, VH 64K, VL 72K,
//                      AH 80K, AL 88K.  total 96K dynamic.
__global__ __launch_bounds__(256) void attn_mma_k(const __nv_bfloat16* __restrict__ bfB,
                                                  const float* __restrict__ log_tau,
                                                  float* __restrict__ y) {
    extern __shared__ unsigned char sm8[];
    __shared__ float redA[64], redS[64];
    const uint32_t sb = smem_u32(sm8);
    int h = blockIdx.y, it = blockIdx.x;
    int t0 = it * 64;
    int tid = threadIdx.x, w = tid >> 5, lane = tid & 31;
    int mw = w >> 2, nw = w & 3;   // 2 x 4 warp grid
    size_t hb = (size_t)h * 64;    // bf16 elems
    float tau = expf(log_tau[h]);

    if (tid < 64) { redA[tid] = 0.f; redS[tid] = 0.f; }

    // load r tiles: arrays {0,1,4,5} -> smem tiles 0..3
    for (int i = tid; i < 2048; i += 256) {
        int tile = i >> 9, idx = i & 511;
        int row = idx >> 3, ch = idx & 7;
        int arr = (tile & 1) + (tile >> 1) * 4;
        const char* g = (const char*)(bfB + (size_t)arr * TD
                        + (size_t)(t0 + row) * 1024 + hb) + ch * 16;
        CPASYNC16(sb + tile * 8192 + SWZ(row * 128 + ch * 16), g);
    }
    CPCOMMIT();
    CPWAIT0();
    __syncthreads();

    float accY[2][2][4];
#pragma unroll
    for (int mt = 0; mt < 2; mt++)
#pragma unroll
        for (int nt = 0; nt < 2; nt++)
#pragma unroll
            for (int q = 0; q < 4; q++) accY[mt][nt][q] = 0.f;
    float sAl[2][2] = {{0.f, 0.f}, {0.f, 0.f}};
    float sSl[2][2] = {{0.f, 0.f}, {0.f, 0.f}};

    for (int jt = 0; jt < 32; jt++) {
        int s0 = jt * 64;
        bool needF = (jt <= it);
        bool needB = (jt >= it);
        // load k1/k2/v tiles: arrays {2,3,6,7,8,9} -> smem 32K + tile*8K
        for (int i = tid; i < 3072; i += 256) {
            int tile = i >> 9;
            if (tile < 2 && !needF) continue;
            if (tile >= 2 && tile < 4 && !needB) continue;
            int idx = i & 511, row = idx >> 3, ch = idx & 7;
            int arr = (tile < 4) ? (2 + (tile & 1) + (tile >> 1) * 4) : (tile + 4);
            const char* g = (const char*)(bfB + (size_t)arr * TD
                            + (size_t)(s0 + row) * 1024 + hb) + ch * 16;
            CPASYNC16(sb + 32768 + tile * 8192 + SWZ(row * 128 + ch * 16), g);
        }
        CPCOMMIT();
        CPWAIT0();
        __syncthreads();

        float accF[2][2][4], accB[2][2][4];
#pragma unroll
        for (int mt = 0; mt < 2; mt++)
#pragma unroll
            for (int nt = 0; nt < 2; nt++)
#pragma unroll
                for (int q = 0; q < 4; q++) { accF[mt][nt][q] = 0.f; accB[mt][nt][q] = 0.f; }

        // ---- scores mma ----
#pragma unroll
        for (int ks = 0; ks < 4; ks++) {
            uint32_t abyte = ks * 32 + (lane >> 4) * 16;
            uint32_t oB = SWZ((nw * 16 + (lane & 15)) * 128 + abyte);
            if (needF) {
                uint32_t aH[2][4], aL[2][4];
#pragma unroll
                for (int mt = 0; mt < 2; mt++) {
                    uint32_t o = SWZ((mw * 32 + mt * 16 + (lane & 15)) * 128 + abyte);
                    LDSM_X4(aH[mt], sb + o);
                    LDSM_X4(aL[mt], sb + 8192 + o);
                }
                uint32_t t4[4], u4[4];
                LDSM_X4(t4, sb + 32768 + oB);
                LDSM_X4(u4, sb + 40960 + oB);
                uint32_t bh[2][2] = {{t4[0], t4[2]}, {t4[1], t4[3]}};
                uint32_t bl[2][2] = {{u4[0], u4[2]}, {u4[1], u4[3]}};
#pragma unroll
                for (int mt = 0; mt < 2; mt++)
#pragma unroll
                    for (int nt = 0; nt < 2; nt++) {
                        MMA16816(accF[mt][nt], aH[mt], bh[nt]);
                        MMA16816(accF[mt][nt], aH[mt], bl[nt]);
                        MMA16816(accF[mt][nt], aL[mt], bh[nt]);
                    }
            }
            if (needB) {
                uint32_t aH[2][4], aL[2][4];
#pragma unroll
                for (int mt = 0; mt < 2; mt++) {
                    uint32_t o = SWZ((mw * 32 + mt * 16 + (lane & 15)) * 128 + abyte);
                    LDSM_X4(aH[mt], sb + 16384 + o);
                    LDSM_X4(aL[mt], sb + 24576 + o);
                }
                uint32_t t4[4], u4[4];
                LDSM_X4(t4, sb + 49152 + oB);
                LDSM_X4(u4, sb + 57344 + oB);
                uint32_t bh[2][2] = {{t4[0], t4[2]}, {t4[1], t4[3]}};
                uint32_t bl[2][2] = {{u4[0], u4[2]}, {u4[1], u4[3]}};
#pragma unroll
                for (int mt = 0; mt < 2; mt++)
#pragma unroll
                    for (int nt = 0; nt < 2; nt++) {
                        MMA16816(accB[mt][nt], aH[mt], bh[nt]);
                        MMA16816(accB[mt][nt], aH[mt], bl[nt]);
                        MMA16816(accB[mt][nt], aL[mt], bh[nt]);
                    }
            }
        }

        // ---- elementwise: select / relu / pow / sums / stash Ash (bf16 hi/lo) ----
        int grp = lane >> 2, qp = lane & 3;
#pragma unroll
        for (int mt = 0; mt < 2; mt++)
#pragma unroll
            for (int nt = 0; nt < 2; nt++)
#pragma unroll
                for (int q = 0; q < 4; q++) {
                    int trow = mw * 32 + mt * 16 + grp + (q >> 1) * 8;
                    int scol = nw * 16 + nt * 8 + qp * 2 + (q & 1);
                    float val;
                    if (jt < it) val = accF[mt][nt][q];
                    else if (jt > it) val = accB[mt][nt][q];
                    else val = (scol > trow) ? accB[mt][nt][q] : accF[mt][nt][q];
                    float a = fmaxf(val, 0.f);
                    sAl[mt][q >> 1] += a;
                    float ash = (a > 0.f) ? __powf(a + 1e-12f, tau) : 0.f;
                    sSl[mt][q >> 1] += ash;
                    __nv_bfloat16 hv = __float2bfloat16(ash);
                    uint32_t o = SWZ((uint32_t)(trow * 128 + scol * 2));
                    *(__nv_bfloat16*)(sm8 + 81920 + o) = hv;
                    *(__nv_bfloat16*)(sm8 + 90112 + o) =
                        __float2bfloat16(ash - __bfloat162float(hv));
                }
        __syncthreads();

        // ---- y mma: accY += Ash @ V ----
#pragma unroll
        for (int ks = 0; ks < 4; ks++) {
            uint32_t abyte = ks * 32 + (lane >> 4) * 16;
            uint32_t aH[2][4], aL[2][4];
#pragma unroll
            for (int mt = 0; mt < 2; mt++) {
                uint32_t o = SWZ((mw * 32 + mt * 16 + (lane & 15)) * 128 + abyte);
                LDSM_X4(aH[mt], sb + 81920 + o);
                LDSM_X4(aL[mt], sb + 90112 + o);
            }
            uint32_t ov = SWZ((ks * 16 + (lane & 15)) * 128 + nw * 32 + (lane >> 4) * 16);
            uint32_t t4[4], u4[4];
            LDSM_X4_T(t4, sb + 65536 + ov);   // vh
            LDSM_X4_T(u4, sb + 73728 + ov);   // vl
            uint32_t bh[2][2] = {{t4[0], t4[1]}, {t4[2], t4[3]}};
            uint32_t bl[2][2] = {{u4[0], u4[1]}, {u4[2], u4[3]}};
#pragma unroll
            for (int mt = 0; mt < 2; mt++)
#pragma unroll
                for (int nt = 0; nt < 2; nt++) {
                    MMA16816(accY[mt][nt], aH[mt], bh[nt]);
                    MMA16816(accY[mt][nt], aH[mt], bl[nt]);
                    MMA16816(accY[mt][nt], aL[mt], bh[nt]);
                }
        }
        __syncthreads();
    }

    // ---- reduce row sums across quad lanes + nw warps ----
    int grp = lane >> 2;
#pragma unroll
    for (int mt = 0; mt < 2; mt++)
#pragma unroll
        for (int qh = 0; qh < 2; qh++) {
            float va = sAl[mt][qh], vs = sSl[mt][qh];
            va += __shfl_xor_sync(0xFFFFFFFFu, va, 1);
            va += __shfl_xor_sync(0xFFFFFFFFu, va, 2);
            vs += __shfl_xor_sync(0xFFFFFFFFu, vs, 1);
            vs += __shfl_xor_sync(0xFFFFFFFFu, vs, 2);
            if ((lane & 3) == 0) {
                int trow = mw * 32 + mt * 16 + grp + qh * 8;
                atomicAdd(&redA[trow], va);
                atomicAdd(&redS[trow], vs);
            }
        }
    __syncthreads();

    // ---- scale + write y ----
    int qp = lane & 3;
#pragma unroll
    for (int mt = 0; mt < 2; mt++) {
        int r0 = mw * 32 + mt * 16 + grp;
        int r1 = r0 + 8;
        float sc0 = fmaxf(redA[r0], 1e-12f) / fmaxf(redS[r0], 1e-12f);
        float sc1 = fmaxf(redA[r1], 1e-12f) / fmaxf(redS[r1], 1e-12f);
#pragma unroll
        for (int nt = 0; nt < 2; nt++) {
            float* d = accY[mt][nt];
            int col = nw * 16 + nt * 8 + qp * 2;
            *(float2*)&y[(size_t)(t0 + r0) * 1024 + hb + col] =
                make_float2(d[0] * sc0, d[1] * sc0);
            *(float2*)&y[(size_t)(t0 + r1) * 1024 + hb + col] =
                make_float2(d[2] * sc1, d[3] * sc1);
        }
    }
}

// ---------------- 10. groupnorm per (t, h) + gate ----------------
__global__ __launch_bounds__(256) void gnorm_k(const float* __restrict__ y,
                                               const float* __restrict__ g,
                                               const float* __restrict__ ln_g,
                                               const float* __restrict__ ln_b,
                                               float* __restrict__ yg) {
    int gw = (blockIdx.x * 256 + threadIdx.x) >> 5;
    int lane = threadIdx.x & 31;
    int t = gw >> 4, h = gw & 15;
    size_t off = (size_t)t * 1024 + h * 64 + lane * 2;
    float2 vv = *(const float2*)(y + off);
    float s = vv.x + vv.y;
    float sq = vv.x * vv.x + vv.y * vv.y;
#pragma unroll
    for (int o = 16; o > 0; o >>= 1) {
        s  += __shfl_xor_sync(0xFFFFFFFFu, s, o);
        sq += __shfl_xor_sync(0xFFFFFFFFu, sq, o);
    }
    float mu = s * (1.f / 64.f);
    float var = sq * (1.f / 64.f) - mu * mu;
    float inv = rsqrtf(var + 6.4e-4f);
    int d = h * 64 + lane * 2;
    float2 gg = *(const float2*)(g + (size_t)t * 1024 + d);
    float2 o;
    o.x = ((vv.x - mu) * inv * ln_g[d]     + ln_b[d])     * gg.x;
    o.y = ((vv.y - mu) * inv * ln_g[d + 1] + ln_b[d + 1]) * gg.y;
    *(float2*)(yg + off) = o;
}

// ---------------- launch ----------------
extern "C" void kernel_launch(void* const* d_in, const int* in_sizes, int n_in,
                              void* d_out, int out_size) {
    const float* x          = (const float*)d_in[0];
    const float* maa_x      = (const float*)d_in[1];
    const float* maa_w      = (const float*)d_in[2];
    const float* maa_k      = (const float*)d_in[3];
    const float* maa_v      = (const float*)d_in[4];
    const float* maa_r      = (const float*)d_in[5];
    const float* maa_g      = (const float*)d_in[6];
    const float* maa_w1     = (const float*)d_in[7];
    const float* maa_w2     = (const float*)d_in[8];
    const float* time_decay = (const float*)d_in[9];
    const float* decay_w1   = (const float*)d_in[10];
    const float* decay_w2   = (const float*)d_in[11];
    const float* log_tau    = (const float*)d_in[12];
    const float* Wr         = (const float*)d_in[13];
    const float* Wk         = (const float*)d_in[14];
    const float* Wv         = (const float*)d_in[15];
    const float* Wg         = (const float*)d_in[16];
    const float* Wo         = (const float*)d_in[17];
    const float* ln_g       = (const float*)d_in[18];
    const float* ln_b       = (const float*)d_in[19];

    float* S = nullptr;
    cudaGetSymbolAddress((void**)&S, g_scratch);
    float* dxb   = S + OFF_DX;
    float* zb    = S + OFF_Z;
    float* xwb   = S + OFF_XW;
    float* xproj = S + OFF_XPROJ;
    float* rkvg  = S + OFF_RKVG;
    float* wb    = S + OFF_W;
    float* csb   = S + OFF_CS;
    float* yb    = S + OFF_Y;
    float* ygb   = S + OFF_YG;
    float* xxxb  = S + OFF_XXX;
    float* wmidb = S + OFF_WMID;
    __nv_bfloat16* actHi = (__nv_bfloat16*)(S + OFF_ACTHI);
    __nv_bfloat16* actLo = (__nv_bfloat16*)(S + OFF_ACTLO);
    __nv_bfloat16* wtHi  = (__nv_bfloat16*)(S + OFF_WTHI);
    __nv_bfloat16* wtLo  = (__nv_bfloat16*)(S + OFF_WTLO);
    __nv_bfloat16* ygHi  = (__nv_bfloat16*)(S + OFF_YGHI);
    __nv_bfloat16* ygLo  = (__nv_bfloat16*)(S + OFF_YGLO);
    __nv_bfloat16* bfB   = (__nv_bfloat16*)(S + OFF_BF);

    int gemm_smem = 131072;
    cudaFuncSetAttribute(gemm_mma_k, cudaFuncAttributeMaxDynamicSharedMemorySize, gemm_smem);
    int attn_smem = 98304;
    cudaFuncSetAttribute(attn_mma_k, cudaFuncAttributeMaxDynamicSharedMemorySize, attn_smem);

    prep_k<<<(TD + 255) / 256, 256>>>(x, maa_x, dxb, zb);
    xxx_k<<<TTOK / 4, 160>>>(zb, maa_w1, xxxb);
    mix_k<<<TTOK / 4, 256>>>(x, dxb, xxxb, maa_w2,
                             maa_w, maa_k, maa_v, maa_r, maa_g, xwb, xproj);
    conv_split_k<<<(4 * TD + 255) / 256, 256>>>(xproj, actHi, actLo, 4 * TD);
    {
        dim3 grid(32, 32, 5);
        conv_wt_k<<<grid, 256>>>(Wr, Wk, Wv, Wg, Wo, wtHi, wtLo);
    }
    {
        dim3 grid(8, 16, 4);
        gemm_mma_k<<<grid, 256, gemm_smem>>>(actHi, actLo, wtHi, wtLo, rkvg, 3);
    }
    decay1_k<<<TTOK / 8, 64>>>(xwb, decay_w1, wmidb);
    decay2_k<<<TTOK / 4, 256>>>(wmidb, decay_w2, time_decay, wb);
    cumsum_k<<<DDIM / 32, 1024>>>(wb, csb);
    premult_bf_k<<<(TD + 255) / 256, 256>>>(rkvg, rkvg + (size_t)TD, wb, csb, bfB);
    conv_split_k<<<(TD + 255) / 256, 256>>>(rkvg + (size_t)2 * TD,
                                            bfB + (size_t)8 * TD, bfB + (size_t)9 * TD, TD);
    {
        dim3 grid(32, 16);
        attn_mma_k<<<grid, 256, attn_smem>>>(bfB, log_tau, yb);
    }
    gnorm_k<<<(TTOK * 16) / 8, 256>>>(yb, rkvg + (size_t)3 * TD, ln_g, ln_b, ygb);
    conv_split_k<<<(TD + 255) / 256, 256>>>(ygb, ygHi, ygLo, TD);
    {
        dim3 grid(8, 16, 1);
        gemm_mma_k<<<grid, 256, gemm_smem>>>(ygHi, ygLo, wtHi + (size_t)4 * 1048576,
                                             wtLo + (size_t)4 * 1048576,
                                             (float*)d_out, -1);
    }
}